// round 1
// baseline (speedup 1.0000x reference)
#include <cuda_runtime.h>
#include <math.h>

#define LSEQ   1024
#define NBATCH 64
#define NCH    64
#define NDIAG  2048          /* 2047 real diagonals, padded to 2048 rows */
#define BIGC   1.0e10f

/* Diagonal-major scratch: Ddiag[b][dd][i] with dd = i + j (0-based), i = row.
   addr = b*NDIAG*LSEQ + dd*LSEQ + i.  512 MB static device scratch. */
__device__ float g_Ddiag[(size_t)NBATCH * NDIAG * LSEQ];

/* ------------------------------------------------------------------ */
/* Kernel A: D[b,i,j] = x2[i] + y2[j] - 2*dot(x_i, y_j), written into  */
/* diagonal-major layout via smem staging (odd-stride pad -> conflict- */
/* free diagonal reads, coalesced global writes along each diagonal).  */
/* ------------------------------------------------------------------ */
__global__ void __launch_bounds__(256)
compute_D_kernel(const float* __restrict__ x, const float* __restrict__ y) {
    const int b  = blockIdx.y;
    const int ti = blockIdx.x >> 4;
    const int tj = blockIdx.x & 15;
    const int i0 = ti * 64, j0 = tj * 64;

    __shared__ float sbuf[2 * 64 * 68];      /* xs[64][68] | ys[64][68]; reused as Dt[64][66] */
    __shared__ float sx2[64], sy2[64];
    float* xs = sbuf;
    float* ys = sbuf + 64 * 68;

    const float* xb = x + ((size_t)b * LSEQ + i0) * NCH;
    const float* yb = y + ((size_t)b * LSEQ + j0) * NCH;

    const int tid = threadIdx.x;

    /* load 64x64 tiles of x and y (coalesced) */
#pragma unroll
    for (int k = 0; k < 16; k++) {
        int e = tid + 256 * k;
        int r = e >> 6, c = e & 63;
        xs[r * 68 + c] = xb[r * NCH + c];
        ys[r * 68 + c] = yb[r * NCH + c];
    }
    __syncthreads();

    /* squared norms */
    if (tid < 64) {
        float s = 0.f;
#pragma unroll
        for (int c = 0; c < 64; c++) { float v = xs[tid * 68 + c]; s += v * v; }
        sx2[tid] = s;
    } else if (tid < 128) {
        int r = tid - 64;
        float s = 0.f;
#pragma unroll
        for (int c = 0; c < 64; c++) { float v = ys[r * 68 + c]; s += v * v; }
        sy2[r] = s;
    }
    __syncthreads();

    /* 4x4 register micro-tile GEMM: dot(x_i, y_j) */
    const int tr = (tid & 15) * 4;   /* i_local base */
    const int tc = (tid >> 4) * 4;   /* j_local base */
    float acc[4][4];
#pragma unroll
    for (int r = 0; r < 4; r++)
#pragma unroll
        for (int s = 0; s < 4; s++) acc[r][s] = 0.f;

#pragma unroll
    for (int c = 0; c < 64; c += 4) {
        float4 xv[4], yv[4];
#pragma unroll
        for (int r = 0; r < 4; r++) xv[r] = *(const float4*)&xs[(tr + r) * 68 + c];
#pragma unroll
        for (int s = 0; s < 4; s++) yv[s] = *(const float4*)&ys[(tc + s) * 68 + c];
#pragma unroll
        for (int r = 0; r < 4; r++)
#pragma unroll
            for (int s = 0; s < 4; s++) {
                acc[r][s] += xv[r].x * yv[s].x + xv[r].y * yv[s].y
                           + xv[r].z * yv[s].z + xv[r].w * yv[s].w;
            }
    }
    __syncthreads();                  /* xs/ys dead -> reuse as Dt */

    float* Dt = sbuf;                 /* [64][66]: stride 66 -> diagonal reads conflict-free */
#pragma unroll
    for (int r = 0; r < 4; r++)
#pragma unroll
        for (int s = 0; s < 4; s++)
            Dt[(tr + r) * 66 + (tc + s)] = sx2[tr + r] + sy2[tc + s] - 2.0f * acc[r][s];
    __syncthreads();

    /* write tile anti-diagonals to global diagonal-major layout (coalesced) */
    float* dst = g_Ddiag + (size_t)b * (NDIAG * LSEQ);
    const int w = tid >> 5, l = tid & 31;
    for (int dl = w; dl < 127; dl += 8) {
        int lo = dl > 63 ? dl - 63 : 0;
        int hi = dl < 63 ? dl : 63;
        int dd = i0 + j0 + dl;
        for (int il = lo + l; il <= hi; il += 32) {
            dst[(size_t)dd * LSEQ + (i0 + il)] = Dt[il * 66 + (dl - il)];
        }
    }
}

/* ------------------------------------------------------------------ */
/* Kernel B: anti-diagonal wavefront, 1 CTA per batch, 1024 threads,  */
/* 3 rotating shared rows -> ONE barrier per diagonal. D prefetched   */
/* one diagonal ahead. Warps fully outside the band skip all MUFU.    */
/* ------------------------------------------------------------------ */
__global__ void __launch_bounds__(1024)
sdtw_wavefront_kernel(float* __restrict__ out) {
    const int b = blockIdx.x;
    const float* Dg = g_Ddiag + (size_t)b * (NDIAG * LSEQ);

    __shared__ float r0s[1032], r1s[1032], r2s[1032];

    const int t  = threadIdx.x;      /* 0..1023 */
    const int ii = t + 1;            /* 1..1024 */

    r0s[ii] = BIGC; r1s[ii] = BIGC; r2s[ii] = BIGC;
    if (t == 0) { r0s[0] = 0.0f; r1s[0] = BIGC; r2s[0] = BIGC; }
    __syncthreads();

    /* rotating buffers: at step d, write buf[d%3], read buf[(d-1)%3], buf[(d-2)%3] */
    float* pw = r2s;   /* d   = 2 */
    float* p1 = r1s;   /* d-1 = 1 */
    float* p2 = r0s;   /* d-2 = 0 */

    const float* dp = Dg + t;        /* row dd = d-2, col i = ii-1 = t */
    float creg  = BIGC;              /* this thread's value on diagonal d-1 (left nbr) */
    float dnext = dp[0];             /* prefetch for d = 2 */
    dp += LSEQ;

    for (int d = 2; d <= 2 * LSEQ; d++) {
        float dval = dnext;
        dnext = dp[0];               /* prefetch d+1 (row d-1 <= 2047, always in-bounds) */
        dp += LSEQ;

        float newv = BIGC;
        /* valid cell: 1 <= j = d-ii <= L  <=>  d-L <= ii <= d-1 */
        bool valid = (ii <= d - 1) && (ii >= d - LSEQ);
        if (valid) {
            float a  = p2[ii - 1];   /* diag  R[i-1][j-1] */
            float up = p1[ii - 1];   /* up    R[i-1][j]   */
            float lf = creg;         /* left  R[i][j-1]   */
            float m  = fminf(fminf(a, up), lf);
            float e  = __expf(m - a) + __expf(m - up) + __expf(m - lf);
            newv = dval + m - __logf(e);
        }
        pw[ii] = newv;
        creg   = newv;
        if (t == 0) pw[0] = BIGC;    /* boundary column stays BIG */
        __syncthreads();

        float* tmp = p2; p2 = p1; p1 = pw; pw = tmp;
    }

    if (t == LSEQ - 1) out[b] = creg;   /* R[L][L] * gamma, gamma = 1 */
}

/* ------------------------------------------------------------------ */
extern "C" void kernel_launch(void* const* d_in, const int* in_sizes, int n_in,
                              void* d_out, int out_size) {
    (void)in_sizes; (void)n_in; (void)out_size;
    const float* x = (const float*)d_in[0];
    const float* y = (const float*)d_in[1];
    float* out = (float*)d_out;

    dim3 gridA(256, NBATCH);
    compute_D_kernel<<<gridA, 256>>>(x, y);
    sdtw_wavefront_kernel<<<NBATCH, 1024>>>(out);
}

// round 2
// speedup vs baseline: 1.9074x; 1.9074x over previous
#include <cuda_runtime.h>
#include <math.h>

#define LSEQ   1024
#define NBATCH 64
#define NCH    64
#define NDIAG  2048
#define BIGC   1.0e10f
#define LOG2E  1.4426950408889634f
#define LN2F   0.6931471805599453f

/* Diagonal-major scratch: Ddiag[b][dd][i], dd = i + j (0-based). */
__device__ float g_Ddiag[(size_t)NBATCH * NDIAG * LSEQ];

__device__ __forceinline__ float ex2(float z) {
    float r; asm("ex2.approx.f32 %0, %1;" : "=f"(r) : "f"(z)); return r;
}
__device__ __forceinline__ float lg2(float z) {
    float r; asm("lg2.approx.f32 %0, %1;" : "=f"(r) : "f"(z)); return r;
}

/* ------------------------------------------------------------------ */
/* Kernel A: D[b,i,j] = (x2[i]+y2[j]-2*dot(x_i,y_j)) * log2(e),        */
/* written diagonal-major. Conflict-free micro-tile: lane q reads     */
/* rows {q,q+16,q+32,q+48} (stride 68 words = 4 banks/lane).           */
/* ------------------------------------------------------------------ */
__global__ void __launch_bounds__(256)
compute_D_kernel(const float* __restrict__ x, const float* __restrict__ y) {
    const int b  = blockIdx.y;
    const int ti = blockIdx.x >> 4;
    const int tj = blockIdx.x & 15;
    const int i0 = ti * 64, j0 = tj * 64;

    __shared__ float sbuf[2 * 64 * 68];    /* xs[64][68] | ys[64][68]; reused as Dt[64][66] */
    __shared__ float sx2[64], sy2[64];
    float* xs = sbuf;
    float* ys = sbuf + 64 * 68;

    const int tid = threadIdx.x;
    const float4* xb4 = (const float4*)(x + ((size_t)b * LSEQ + i0) * NCH);
    const float4* yb4 = (const float4*)(y + ((size_t)b * LSEQ + j0) * NCH);

#pragma unroll
    for (int k = 0; k < 4; k++) {
        int e = tid + 256 * k;          /* 0..1023 */
        int r = e >> 4, c4 = e & 15;
        *(float4*)&xs[r * 68 + c4 * 4] = xb4[r * 16 + c4];
        *(float4*)&ys[r * 68 + c4 * 4] = yb4[r * 16 + c4];
    }
    __syncthreads();

    if (tid < 64) {
        float s = 0.f;
#pragma unroll
        for (int c = 0; c < 64; c++) { float v = xs[tid * 68 + c]; s += v * v; }
        sx2[tid] = s;
    } else if (tid < 128) {
        int r = tid - 64;
        float s = 0.f;
#pragma unroll
        for (int c = 0; c < 64; c++) { float v = ys[r * 68 + c]; s += v * v; }
        sy2[r] = s;
    }
    __syncthreads();

    const int q = tid & 15;     /* row lane */
    const int p = tid >> 4;     /* col group */
    float acc[4][4];
#pragma unroll
    for (int r = 0; r < 4; r++)
#pragma unroll
        for (int s = 0; s < 4; s++) acc[r][s] = 0.f;

#pragma unroll
    for (int c = 0; c < 64; c += 4) {
        float4 xv[4], yv[4];
#pragma unroll
        for (int r = 0; r < 4; r++) xv[r] = *(const float4*)&xs[(q + 16 * r) * 68 + c];
#pragma unroll
        for (int s = 0; s < 4; s++) yv[s] = *(const float4*)&ys[(p + 16 * s) * 68 + c];
#pragma unroll
        for (int r = 0; r < 4; r++)
#pragma unroll
            for (int s = 0; s < 4; s++) {
                acc[r][s] += xv[r].x * yv[s].x + xv[r].y * yv[s].y
                           + xv[r].z * yv[s].z + xv[r].w * yv[s].w;
            }
    }
    __syncthreads();            /* xs/ys dead -> reuse as Dt */

    float* Dt = sbuf;           /* [64][66] */
#pragma unroll
    for (int r = 0; r < 4; r++)
#pragma unroll
        for (int s = 0; s < 4; s++) {
            int rr = q + 16 * r, cc = p + 16 * s;
            Dt[rr * 66 + cc] = (sx2[rr] + sy2[cc] - 2.0f * acc[r][s]) * LOG2E;
        }
    __syncthreads();

    float* dst = g_Ddiag + (size_t)b * (NDIAG * LSEQ);
    const int w = tid >> 5, l = tid & 31;
    for (int dl = w; dl < 127; dl += 8) {
        int lo = dl > 63 ? dl - 63 : 0;
        int hi = dl < 63 ? dl : 63;
        int dd = i0 + j0 + dl;
        for (int il = lo + l; il <= hi; il += 32) {
            dst[(size_t)dd * LSEQ + (i0 + il)] = Dt[il * 66 + (dl - il)];
        }
    }
}

/* ------------------------------------------------------------------ */
/* Kernel B: register-pipelined soft-DTW. Warp w owns rows            */
/* [32w, 32w+32); lane l carries row 32w+l recurrence in registers.   */
/* Neighbor row via shfl_up; strip boundary via 128-entry smem ring;  */
/* warps skewed 3 rounds (48 steps); one __syncthreads per 16-step    */
/* round. All values in base-2 domain (D pre-scaled by log2(e)).      */
/* ------------------------------------------------------------------ */
#define CH      16
#define NCHUNK  66                      /* 66*16 = 1056 >= 1055 local steps */
#define KOFF    3                       /* rounds of skew per warp */
#define NROUNDS (KOFF * 31 + NCHUNK)    /* 159 */

__global__ void __launch_bounds__(1024)
sdtw_pipeline_kernel(float* __restrict__ out) {
    const int b = blockIdx.x;
    const int tid = threadIdx.x;
    const int w = tid >> 5;
    const int l = tid & 31;

    __shared__ float rb[31][128];       /* boundary ring: rb[w] written by warp w lane 31 */

    /* init rings to BIG (slot 0 = R[row][0] boundary must be BIG) */
    for (int e = tid; e < 31 * 128; e += 1024) ((float*)rb)[e] = BIGC;
    __syncthreads();

    float v1 = BIGC;                    /* own value at local step s-1  (left) */
    float v2 = BIGC;                    /* own value at local step s-2         */
    float d0 = BIGC;                    /* lane0: boundary value Rb[w-1][J-1]  */

    const float* dp = g_Ddiag + ((size_t)b << 21)
                    + (size_t)(w * 32) * LSEQ + (w * 32 + l);
    float*       rbw = (w < 31) ? rb[w] : rb[0];   /* write ring (w=31 writes none) */
    const float* rbr = (w > 0) ? rb[w - 1] : rb[0];

    float result = 0.0f;

    for (int r = 0; r < NROUNDS; r++) {
        const int c = r - KOFF * w;
        if (c >= 0 && c < NCHUNK) {
            const int sc = c * CH;
            /* prefetch this chunk's D values (coalesced across warp per step) */
            float dv[CH];
            const float* dpc = dp + (size_t)sc * LSEQ;
#pragma unroll
            for (int k = 0; k < CH; k++) dv[k] = dpc[(size_t)k * LSEQ];

#pragma unroll
            for (int k = 0; k < CH; k++) {
                const int s = sc + k;
                float a = __shfl_up_sync(0xffffffffu, v2, 1);  /* diag R[i-1][j-1] */
                float u = __shfl_up_sync(0xffffffffu, v1, 1);  /* up   R[i-1][j]   */
                if (l == 0) {
                    if (w == 0) { u = BIGC; a = (s == 0) ? 0.0f : BIGC; }
                    else        { u = rbr[(s + 1) & 127]; a = d0; d0 = u; }
                }
                bool act = (s >= l) && (s <= 1023 + l);
                if (act) {
                    float lf  = v1;
                    float mn1 = fminf(a, u);
                    float mx1 = fmaxf(a, u);
                    float m   = fminf(mn1, lf);
                    float M   = fmaxf(mx1, lf);
                    float med = fmaxf(mn1, fminf(mx1, lf));
                    float e   = 1.0f + ex2(m - med) + ex2(m - M);
                    float nv  = dv[k] + m - lg2(e);
                    v2 = v1; v1 = nv;
                    if (l == 31) {
                        if (w < 31) rbw[(s - 30) & 127] = nv;
                        else if (s == 1054) result = nv;   /* R[1024][1024] */
                    }
                }
            }
        }
        __syncthreads();
    }

    if (w == 31 && l == 31) out[b] = result * LN2F;
}

/* ------------------------------------------------------------------ */
extern "C" void kernel_launch(void* const* d_in, const int* in_sizes, int n_in,
                              void* d_out, int out_size) {
    (void)in_sizes; (void)n_in; (void)out_size;
    const float* x = (const float*)d_in[0];
    const float* y = (const float*)d_in[1];
    float* out = (float*)d_out;

    dim3 gridA(256, NBATCH);
    compute_D_kernel<<<gridA, 256>>>(x, y);
    sdtw_pipeline_kernel<<<NBATCH, 1024>>>(out);
}